// round 17
// baseline (speedup 1.0000x reference)
#include <cuda_runtime.h>
#include <cuda_fp16.h>
#include <cstdint>
#include <cstddef>

// ============================================================================
// MotionGenerator fused: masked-conv1d(stride2,reflect7,K15)+pool+leakyReLU
// via mma.sync.m16n8k16 fp16 single-term (Ah*Bh), fp32 accum.
// R17 = R14/R16 body + STATIC BALANCED BINS: 304 CTAs (152 SMs x 2), each
// processes a precomputed list of (g,tile,b) items; bins sum to 35-36
// nj-units (ideal 35.79) -> wave quantization eliminated.
//   bins   0- 63: {9,9,9,8}        = 35
//   bins  64-191: {11,9,4,4,4,4}   = 36
//   bins 192-239: {9,9,9,9}        = 36
//   bins 240-303: {8,7,7,7,7}      = 36
// Pools: 11->g1, 9->{g3,g5,g7,g9}, 8->g0, 7->{g2,g11}, 4->{g4,g6,g8,g10};
// instance idx&127 -> (tile = &15, b = >>4). Every item covered exactly once.
// ============================================================================

#define NG 12
#define NSLOT 85
#define NBINS 304

__constant__ int   cOff[NG + 1] = {0, 8, 19, 26, 35, 39, 48, 52, 61, 65, 74, 78, 85};
__constant__ int   cE0[NG] = {0, 1, 3, 4, 6, 8, 10, 12, 14, 16, 18, 20};
__constant__ int   cE1[NG] = {-1, 2, -1, 5, 7, 9, 11, 13, 15, 17, 19, -1};

__constant__ int cSlotG[NSLOT] = {
    0,0,0,0,0,0,0,0,
    1,1,1,1,1,1,1,1,1,1,1,
    2,2,2,2,2,2,2,
    3,3,3,3,3,3,3,3,3,
    4,4,4,4,
    5,5,5,5,5,5,5,5,5,
    6,6,6,6,
    7,7,7,7,7,7,7,7,7,
    8,8,8,8,
    9,9,9,9,9,9,9,9,9,
    10,10,10,10,
    11,11,11,11,11,11,11
};

__constant__ int cJ[NSLOT] = {
    0,1,2,12,13,16,17,20,
    0,1,2,3,4,5,8,9,12,16,20,
    1,2,3,4,5,8,9,
    1,2,3,4,5,6,7,8,9,
    4,5,6,7,
    1,2,3,4,5,8,9,10,11,
    8,9,10,11,
    0,1,12,13,14,15,16,17,20,
    12,13,14,15,
    0,1,12,13,16,17,18,19,20,
    16,17,18,19,
    0,1,2,12,13,16,17
};

__constant__ float cC0[NSLOT] = {
    1,1,1,1,1,1,1,1,
    0.5f,0.5f,0.5f,0.5f,0.5f,0.0f,0.5f,0.0f,0.5f,0.5f,0.5f,
    1,1,1,1,1,1,1,
    0.5f,0.5f,0.5f,0.5f,0.5f,0.5f,0.0f,0.5f,0.5f,
    0.5f,0.5f,0.5f,0.5f,
    0.5f,0.5f,0.5f,0.5f,0.5f,0.5f,0.5f,0.5f,0.0f,
    0.5f,0.5f,0.5f,0.5f,
    0.5f,0.5f,0.5f,0.5f,0.5f,0.0f,0.5f,0.5f,0.5f,
    0.5f,0.5f,0.5f,0.5f,
    0.5f,0.5f,0.5f,0.5f,0.5f,0.5f,0.5f,0.0f,0.5f,
    0.5f,0.5f,0.5f,0.5f,
    1,1,1,1,1,1,1
};

__constant__ float cC1[NSLOT] = {
    0,0,0,0,0,0,0,0,
    0.5f,0.5f,0.5f,0.5f,0.5f,0.5f,0.5f,0.5f,0.0f,0.0f,0.5f,
    0,0,0,0,0,0,0,
    0.0f,0.5f,0.5f,0.5f,0.5f,0.5f,0.5f,0.5f,0.0f,
    0.0f,0.5f,0.5f,0.5f,
    0.0f,0.5f,0.5f,0.5f,0.0f,0.5f,0.5f,0.5f,0.5f,
    0.0f,0.5f,0.5f,0.5f,
    0.5f,0.0f,0.5f,0.5f,0.5f,0.5f,0.5f,0.0f,0.5f,
    0.0f,0.5f,0.5f,0.5f,
    0.5f,0.0f,0.5f,0.0f,0.5f,0.5f,0.5f,0.5f,0.5f,
    0.0f,0.5f,0.5f,0.5f,
    0,0,0,0,0,0,0
};

// Folded weights, fp16, dense [s][k][oc=128][ci=64]
__device__ __align__(16) __half g_Wh[(size_t)NSLOT * 15 * 8192];

// ---------------------------------------------------------------------------
#define AP    72
#define AROWS 136
#define ASZ   (AROWS * AP)             // 9792 halves per parity
#define A_OFF 512
#define B_OFF (A_OFF + 2 * ASZ * 2)    // 39680
#define BSLICE 4608                    // 32 rows * 144 B
#define SMEM_BYTES (B_OFF + 8 * 2 * BSLICE)   // 113408

__device__ __forceinline__ uint32_t smem_u32(const void* p) {
    uint32_t a;
    asm("{ .reg .u64 t; cvta.to.shared.u64 t, %1; cvt.u32.u64 %0, t; }" : "=r"(a) : "l"(p));
    return a;
}

__device__ __forceinline__ void mma16816(float* d, const uint32_t* a,
                                         uint32_t b0, uint32_t b1) {
    asm volatile(
        "mma.sync.aligned.m16n8k16.row.col.f32.f16.f16.f32 "
        "{%0,%1,%2,%3}, {%4,%5,%6,%7}, {%8,%9}, {%0,%1,%2,%3};"
        : "+f"(d[0]), "+f"(d[1]), "+f"(d[2]), "+f"(d[3])
        : "r"(a[0]), "r"(a[1]), "r"(a[2]), "r"(a[3]), "r"(b0), "r"(b1));
}

__device__ __forceinline__ void ldmx4(uint32_t* r, uint32_t addr) {
    asm volatile("ldmatrix.sync.aligned.m8n8.x4.shared.b16 {%0,%1,%2,%3}, [%4];"
                 : "=r"(r[0]), "=r"(r[1]), "=r"(r[2]), "=r"(r[3]) : "r"(addr));
}

__device__ __forceinline__ uint32_t pkh2(float hi, float lo) {
    uint32_t d;
    asm("cvt.rn.f16x2.f32 %0, %1, %2;" : "=r"(d) : "f"(hi), "f"(lo));
    return d;
}

// closed-form bin decode: (bin s, slot t) -> (g, tb). Pools:
//   9-pool idx 0..511 -> g = 3 + 2*(idx>>7);  4-pool idx 0..511 -> g = 4 + 2*(idx>>7)
//   7-pool idx 0..255 -> g = (idx>>7) ? 11 : 2;  8 -> g0; 11 -> g1
__device__ __forceinline__ void decode_item(int s, int t, int& g, int& tb) {
    if (s < 64) {                       // {9,9,9,8}
        if (t < 3) { int idx = 3 * s + t; g = 3 + 2 * (idx >> 7); tb = idx & 127; }
        else       { g = 0; tb = s; }
    } else if (s < 192) {               // {11,9,4,4,4,4}
        const int sp = s - 64;
        if (t == 0)      { g = 1; tb = sp; }
        else if (t == 1) { int idx = 192 + sp; g = 3 + 2 * (idx >> 7); tb = idx & 127; }
        else             { int idx = 4 * sp + (t - 2); g = 4 + 2 * (idx >> 7); tb = idx & 127; }
    } else if (s < 240) {               // {9,9,9,9}
        const int sp = s - 192;
        int idx = 320 + 4 * sp + t; g = 3 + 2 * (idx >> 7); tb = idx & 127;
    } else {                            // {8,7,7,7,7}
        const int sp = s - 240;
        if (t == 0) { g = 0; tb = 64 + sp; }
        else        { int idx = 4 * sp + (t - 1); g = (idx >> 7) ? 11 : 2; tb = idx & 127; }
    }
}
__device__ __forceinline__ int bin_count(int s) {
    return (s < 64) ? 4 : (s < 192) ? 6 : (s < 240) ? 4 : 5;
}

// ---------------------------------------------------------------------------
__global__ void prep_wc(const float* __restrict__ weight) {
    const int s  = blockIdx.x;
    const int oc = blockIdx.y;
    const int g  = cSlotG[s];
    const int j  = cJ[s];
    const float c0 = cC0[s], c1 = cC1[s];
    const int e0 = cE0[g], e1 = cE1[g];

    const float* __restrict__ w0 = weight + (size_t)(e0 * 128 + oc) * 20160 + (size_t)j * 960;
    const float* __restrict__ w1 = (e1 >= 0)
        ? weight + (size_t)(e1 * 128 + oc) * 20160 + (size_t)j * 960 : nullptr;

    for (int q = threadIdx.x; q < 960; q += blockDim.x) {
        float v = c0 * w0[q];
        if (w1) v += c1 * w1[q];
        const int ci = q / 15;
        const int k  = q - ci * 15;
        g_Wh[((size_t)(s * 15 + k) * 128 + oc) * 64 + ci] = __float2half_rn(v);
    }
}

// ---------------------------------------------------------------------------
// Main: 304 CTAs x 256 threads; each CTA runs its bin's items sequentially.
// Per item: tile 128t x 128oc, 8 warps (2 t-groups x 4 oc-slices).
// ---------------------------------------------------------------------------
__global__ __launch_bounds__(256, 2)
void motion_hmma(const float* __restrict__ x,
                 const float* __restrict__ bias,
                 float* __restrict__ out) {
    extern __shared__ __align__(16) char smem[];
    float* sbias = reinterpret_cast<float*>(smem);
    __half* Aarr = reinterpret_cast<__half*>(smem + A_OFF);
    const uint32_t Asm = smem_u32(Aarr);
    const uint32_t Bsm = smem_u32(smem + B_OFF);

    const int tid  = threadIdx.x;
    const int w    = tid >> 5;       // 0..7
    const int lane = tid & 31;
    const int sbin = blockIdx.x;     // 0..303

    const int warp_tm = (w & 1) * 64;
    const int warp_on = (w >> 1) * 32;
    const uint32_t Bwarp = Bsm + (uint32_t)w * (2 * BSLICE);

    // per-lane ldmatrix address components
    const uint32_t aoff = (uint32_t)(lane & 15) * 144 + ((lane >> 4) ? 16u : 0u);
    const uint32_t boff = (uint32_t)(((lane >> 4) & 1) * 8 + (lane & 7)) * 144
                        + (((lane >> 3) & 1) ? 16u : 0u);

    const int nitems = bin_count(sbin);

    for (int it = 0; it < nitems; ++it) {
        int g, tb;
        decode_item(sbin, it, g, tb);
        const int tile = tb & 15;
        const int b    = tb >> 4;
        const int t0   = tile << 7;
        const int base = 2 * t0 - 7;
        const bool interior = (tile >= 1) && (tile <= 14);

        __syncthreads();   // prior item's epilogue reads done before sbias/A reuse

        if (tid < 128) {
            const int e0 = cE0[g], e1 = cE1[g];
            float bv = bias[e0 * 128 + tid];
            if (e1 >= 0) bv = 0.5f * (bv + bias[e1 * 128 + tid]);
            sbias[tid] = bv;
        }

        float acc[4][4][4];
#pragma unroll
        for (int mi = 0; mi < 4; ++mi)
#pragma unroll
            for (int ni = 0; ni < 4; ++ni)
#pragma unroll
                for (int q = 0; q < 4; ++q) acc[mi][ni][q] = 0.f;

        const int off0 = cOff[g];
        const int nj   = cOff[g + 1] - off0;
        const int nt   = nj * 15;

        // warp-private cp.async: this warp's 32-oc slice of tap n -> buf n&1
        auto issue = [&](int n) {
            const int s = off0 + n / 15;
            const int k = n - (n / 15) * 15;
            const __half* __restrict__ tbw =
                g_Wh + (size_t)(s * 15 + k) * 8192 + (size_t)warp_on * 64;
            const uint32_t dbase = Bwarp + (uint32_t)(n & 1) * BSLICE;
#pragma unroll
            for (int i = 0; i < 8; ++i) {
                const int c   = lane + (i << 5);      // 0..255
                const int row = c >> 3;               // 0..31 (local oc)
                const int col = c & 7;                // 16B chunk
                const __half* src = tbw + (size_t)row * 64 + col * 8;
                const uint32_t dst = dbase + row * 144 + col * 16;
                asm volatile("cp.async.cg.shared.global [%0], [%1], 16;"
                             :: "r"(dst), "l"(src) : "memory");
            }
            asm volatile("cp.async.commit_group;" ::: "memory");
        };

        issue(0);
        if (nt > 1) issue(1);

        for (int jj = 0; jj < nj; ++jj) {
            const int j = cJ[off0 + jj];

            __syncthreads();   // all warps done reading previous joint's A window

            // ---- window load: x -> A[parity][q][ci] fp16 ----
            const float* __restrict__ xj = x + ((size_t)b * 1344 + (size_t)j * 64) * 4096;
            if (interior) {
                const float* __restrict__ r0p =
                    xj + (size_t)(2 * lane) * 4096 + (2 * t0 - 8);
                const float* __restrict__ r1p = r0p + 4096;
                uint32_t* __restrict__ Ae32 =
                    reinterpret_cast<uint32_t*>(Aarr) + lane;          // row stride 36 u32
                uint32_t* __restrict__ Ao32 = Ae32 + (ASZ >> 1);
#pragma unroll
                for (int i = 0; i < 9; ++i) {
                    const int c = w + 8 * i;
                    if (c >= 68) break;
                    const float4 fa = *reinterpret_cast<const float4*>(r0p + 4 * c);
                    const float4 fb = *reinterpret_cast<const float4*>(r1p + 4 * c);
                    if (c > 0) Ao32[(size_t)(2 * c - 1) * 36] = pkh2(fb.x, fa.x);
                    Ae32[(size_t)(2 * c    ) * 36] = pkh2(fb.y, fa.y);
                    Ao32[(size_t)(2 * c    ) * 36] = pkh2(fb.z, fa.z);
                    Ae32[(size_t)(2 * c + 1) * 36] = pkh2(fb.w, fa.w);
                }
            } else {
                for (int ci = w; ci < 64; ci += 8) {
                    const float* __restrict__ src = xj + (size_t)ci * 4096;
                    for (int r = lane; r < 269; r += 32) {
                        int pos = base + r;
                        pos = pos < 0 ? -pos : pos;
                        pos = pos > 4095 ? 8190 - pos : pos;
                        Aarr[(size_t)(r & 1) * ASZ + (r >> 1) * AP + ci] =
                            __float2half_rn(src[pos]);
                    }
                }
            }
            __syncthreads();   // A visible to all warps

            // ---- 15 taps, no CTA barriers: warp-private B rings ----
            for (int k = 0; k < 15; ++k) {
                const int n = jj * 15 + k;

                if (n + 1 < nt) {
                    asm volatile("cp.async.wait_group 1;" ::: "memory");
                } else {
                    asm volatile("cp.async.wait_group 0;" ::: "memory");
                }

                const uint32_t Ap = Asm + (uint32_t)(k & 1) * (ASZ * 2)
                                  + (uint32_t)(warp_tm + (k >> 1)) * 144 + aoff;
                const uint32_t Bp = Bwarp + (uint32_t)(n & 1) * BSLICE + boff;

#pragma unroll
                for (int cc = 0; cc < 4; ++cc) {
                    uint32_t a[4][4];
#pragma unroll
                    for (int mi = 0; mi < 4; ++mi)
                        ldmx4(a[mi], Ap + cc * 32 + mi * (16 * 144));
#pragma unroll
                    for (int p = 0; p < 2; ++p) {
                        uint32_t bb[4];
                        ldmx4(bb, Bp + cc * 32 + p * (16 * 144));
#pragma unroll
                        for (int mi = 0; mi < 4; ++mi) {
                            mma16816(acc[mi][2 * p],     a[mi], bb[0], bb[1]);
                            mma16816(acc[mi][2 * p + 1], a[mi], bb[2], bb[3]);
                        }
                    }
                }

                if (n + 2 < nt) issue(n + 2);   // refill ring (warp-private)
            }
        }

        __syncthreads();   // all MMAs done before staging overwrites A/B regions

        // ---- epilogue: transpose D via smem, bias + leaky relu ----
        float* Ds = reinterpret_cast<float*>(smem + A_OFF);   // [oc=128][132]
        {
            const int grow = lane >> 2;
            const int colb = (lane & 3) * 2;
#pragma unroll
            for (int mi = 0; mi < 4; ++mi) {
                const int row = warp_tm + mi * 16 + grow;
#pragma unroll
                for (int ni = 0; ni < 4; ++ni) {
                    const int col = warp_on + ni * 8 + colb;
                    Ds[(col    ) * 132 + row    ] = acc[mi][ni][0];
                    Ds[(col + 1) * 132 + row    ] = acc[mi][ni][1];
                    Ds[(col    ) * 132 + row + 8] = acc[mi][ni][2];
                    Ds[(col + 1) * 132 + row + 8] = acc[mi][ni][3];
                }
            }
        }
        __syncthreads();

        {
            const int oc = tid >> 1, half = tid & 1;
            const float bv = sbias[oc];
            const float4* __restrict__ sp =
                reinterpret_cast<const float4*>(Ds + oc * 132 + half * 64);
            float4* __restrict__ op = reinterpret_cast<float4*>(
                out + ((size_t)b * 1536 + (size_t)g * 128 + oc) * 2048 + t0 + half * 64);
#pragma unroll
            for (int i = 0; i < 16; ++i) {
                float4 v = sp[i];
                v.x += bv; v.y += bv; v.z += bv; v.w += bv;
                v.x = v.x > 0.f ? v.x : 0.2f * v.x;
                v.y = v.y > 0.f ? v.y : 0.2f * v.y;
                v.z = v.z > 0.f ? v.z : 0.2f * v.z;
                v.w = v.w > 0.f ? v.w : 0.2f * v.w;
                op[i] = v;
            }
        }
    }
}

// ---------------------------------------------------------------------------
extern "C" void kernel_launch(void* const* d_in, const int* in_sizes, int n_in,
                              void* d_out, int out_size) {
    (void)in_sizes; (void)n_in; (void)out_size;
    const float* x      = (const float*)d_in[0];   // [8][1344][4096]
    const float* weight = (const float*)d_in[1];   // [2688][1344][15]
    const float* bias   = (const float*)d_in[2];   // [2688]
    float* out          = (float*)d_out;           // [8][1536][2048]

    cudaFuncSetAttribute(motion_hmma, cudaFuncAttributeMaxDynamicSharedMemorySize,
                         SMEM_BYTES);

    dim3 gp(NSLOT, 128);
    prep_wc<<<gp, 256>>>(weight);

    motion_hmma<<<NBINS, 256, SMEM_BYTES>>>(x, bias, out);
}